// round 13
// baseline (speedup 1.0000x reference)
#include <cuda_runtime.h>
#include <cuda_fp16.h>
#include <cstdint>

// ---------------------------------------------------------------------------
// ContrastivePatchLoss — fused persistent kernel: producer CTAs convert
// banks+anchors, consumer CTAs run HMMA f16-acc GEMM+softmax with spin-wait
// dependencies. Split (M,S) partials merged by a small epilogue kernel.
// ---------------------------------------------------------------------------

#define NPATCH   512
#define ROWS_TOT 32768
#define NBANK    2048
#define EPSV     1e-5f
#define SCALEF   2.8853900817779268f   // (1/0.5) * log2(e)
#define NEG_HUGE (-1e30f)
#define TILEB    65536                 // 128 rows x 512 B
#define NUNITS   1024                  // 256 q x 4 col-quarters
#define NCONV    1088                  // 64 bank units + 1024 anchor units
#define NPROD    56                    // producer CTAs

// g_A blocked: [slot(512)][yin(8)][c(256)][xin(8)] fp16
__device__ __half g_A[ROWS_TOT * 256];
// banks pre-swizzled: [tile(16)][row(128)][c'(32) x 16B], c' = (c&24)|((c^row)&7)
__device__ __half g_negB[NBANK * 256];
__device__ __half g_posB[NBANK * 256];
__device__ float g_pos_sim[ROWS_TOT];
__device__ int   g_flags[NPATCH];
__device__ int   g_slot[NPATCH];
__device__ int   g_sgrp[NPATCH];                  // slot -> group (b*8+j)
__device__ int   g_pairinfo[256];
__device__ int   g_ctr;                           // GEMM unit queue
__device__ int   g_ctr_conv;                      // conversion unit queue
__device__ int   g_grpcnt[64];                    // anchor group counters (->16)
__device__ int   g_bankcnt[32];                   // bank tile counters (->2)
__device__ float2 g_pms[NUNITS * 128];            // per-(unit,row) partial (M,S)
__device__ float g_part[128];

// ---------------------------------------------------------------------------
__device__ __forceinline__ unsigned sm2u(const void* p) {
    return (unsigned)__cvta_generic_to_shared(p);
}
__device__ __forceinline__ float ex2f(float x) {
    float y; asm("ex2.approx.f32 %0, %1;" : "=f"(y) : "f"(x)); return y;
}
__device__ __forceinline__ __half2 h2ex2(__half2 x) {
    __half2 y;
    asm("ex2.approx.f16x2 %0, %1;" : "=r"(*(unsigned*)&y) : "r"(*(unsigned*)&x));
    return y;
}
__device__ __forceinline__ __half2 u2h2(unsigned u) { return *(__half2*)&u; }
__device__ __forceinline__ void ldsm4(unsigned& r0, unsigned& r1, unsigned& r2, unsigned& r3,
                                      unsigned addr) {
    asm volatile("ldmatrix.sync.aligned.m8n8.x4.shared.b16 {%0,%1,%2,%3}, [%4];\n"
                 : "=r"(r0), "=r"(r1), "=r"(r2), "=r"(r3) : "r"(addr));
}
__device__ __forceinline__ void ldsm4t(unsigned& r0, unsigned& r1, unsigned& r2, unsigned& r3,
                                       unsigned addr) {
    asm volatile("ldmatrix.sync.aligned.m8n8.x4.trans.shared.b16 {%0,%1,%2,%3}, [%4];\n"
                 : "=r"(r0), "=r"(r1), "=r"(r2), "=r"(r3) : "r"(addr));
}
__device__ __forceinline__ void mma_f16(unsigned& c0, unsigned& c1,
                                        unsigned a0, unsigned a1, unsigned a2, unsigned a3,
                                        unsigned b0, unsigned b1) {
    asm volatile("mma.sync.aligned.m16n8k16.row.col.f16.f16.f16.f16 "
                 "{%0,%1},{%2,%3,%4,%5},{%6,%7},{%0,%1};\n"
                 : "+r"(c0), "+r"(c1)
                 : "r"(a0), "r"(a1), "r"(a2), "r"(a3), "r"(b0), "r"(b1));
}
__device__ __forceinline__ void mbar_wait(unsigned addr, unsigned parity) {
    asm volatile("{\n\t.reg .pred P;\n"
                 "W%=:\n\tmbarrier.try_wait.parity.shared.b64 P, [%0], %1;\n"
                 "\t@P bra D%=;\n\tbra W%=;\nD%=:\n\t}"
                 :: "r"(addr), "r"(parity) : "memory");
}
__device__ __forceinline__ void mbar_expect(unsigned addr, unsigned bytes) {
    asm volatile("mbarrier.arrive.expect_tx.shared.b64 _, [%0], %1;"
                 :: "r"(addr), "r"(bytes) : "memory");
}
__device__ __forceinline__ void bulk_copy(unsigned dst, const void* src, unsigned bytes,
                                          unsigned mbar) {
    asm volatile("cp.async.bulk.shared::cluster.global.mbarrier::complete_tx::bytes "
                 "[%0], [%1], %2, [%3];"
                 :: "r"(dst), "l"(src), "r"(bytes), "r"(mbar) : "memory");
}

// ---------------------------------------------------------------------------
// 1) label patch means -> flags; also zeroes g_pos_sim for the atomic combine
// ---------------------------------------------------------------------------
__global__ void label_kernel(const float* __restrict__ lab) {
    __shared__ float sred[8];
    const int p = blockIdx.x, t = threadIdx.x;
    if (t < 64) g_pos_sim[p * 64 + t] = 0.f;
    const int b = p >> 6, j = (p >> 3) & 7, k = p & 7;
    const float* base = lab + (size_t)b * 65536 + (size_t)j * 32 * 256 + k * 32;
    float sum = 0.f;
#pragma unroll
    for (int it = 0; it < 4; ++it) {
        int u = t + 256 * it;
        int y = u >> 5, x = u & 31;
        sum += base[y * 256 + x];
    }
#pragma unroll
    for (int o = 16; o; o >>= 1) sum += __shfl_xor_sync(~0u, sum, o);
    if ((t & 31) == 0) sred[t >> 5] = sum;
    __syncthreads();
    if (t == 0) {
        float s2 = 0.f;
#pragma unroll
        for (int i = 0; i < 8; ++i) s2 += sred[i];
        g_flags[p] = (s2 * (1.f / 1024.f) < 0.1f) ? 1 : 0;
    }
}

// ---------------------------------------------------------------------------
// 2) permutation + all counter resets + slot->group map
// ---------------------------------------------------------------------------
__global__ void perm_kernel() {
    __shared__ int sc[512], sflag[512];
    const int t = threadIdx.x;
    if (t == 0) { g_ctr = 0; g_ctr_conv = 0; }
    if (t < 64) g_grpcnt[t] = 0;
    if (t < 32) g_bankcnt[t] = 0;
    const int f = g_flags[t];
    sc[t] = f;
    __syncthreads();
    for (int off = 1; off < 512; off <<= 1) {
        int add = (t >= off) ? sc[t - off] : 0;
        __syncthreads();
        sc[t] += add;
        __syncthreads();
    }
    const int npos = sc[511];
    const int slot = f ? (sc[t] - 1) : (npos + t - sc[t]);
    g_slot[t] = slot;
    g_sgrp[slot] = t >> 3;                        // group = b*8+j
    sflag[slot] = f;
    __syncthreads();
    if (t < 256) g_pairinfo[t] = sflag[2 * t] | (sflag[2 * t + 1] << 1);
}

// ---------------------------------------------------------------------------
// producer unit: bank conversion (u in [0,64))
// ---------------------------------------------------------------------------
__device__ void bank_unit(int u, const float* __restrict__ neg,
                          const float* __restrict__ pos, char* stage) {
    __half (*sT)[66] = (__half(*)[66])stage;
    const int t = threadIdx.x;
    const int bank = u >> 5, l = u & 31;
    const float* src = (bank ? pos : neg) + (size_t)l * 16384;
    __syncthreads();
#pragma unroll 4
    for (int it = 0; it < 64; ++it) {
        int u2 = t + 256 * it;
        int c = u2 >> 6, s = u2 & 63;
        sT[c][s] = __float2half(src[c * 64 + s]);
    }
    __syncthreads();
    unsigned* dst32 = (unsigned*)((bank ? g_posB : g_negB));
    const int tile = l >> 1;
    const int rbase = (l & 1) * 64;
#pragma unroll 4
    for (int it = 0; it < 32; ++it) {
        int u2 = t + 256 * it;
        int s = u2 >> 7, cc = u2 & 127;
        unsigned lo = __half_as_ushort(sT[2 * cc][s]);
        unsigned hi = __half_as_ushort(sT[2 * cc + 1][s]);
        const int row = rbase + s;
        const int c16 = cc >> 2;
        const int csw = (c16 & 24) | ((c16 ^ row) & 7);
        dst32[(tile * 65536 + row * 512 + csw * 16 + (cc & 3) * 4) >> 2] = (hi << 16) | lo;
    }
    __threadfence();
    __syncthreads();
    if (t == 0) atomicAdd(&g_bankcnt[bank * 16 + tile], 1);
}

// ---------------------------------------------------------------------------
// producer unit: anchor conversion (bid0 in [0,1024)) — R11 layout
// ---------------------------------------------------------------------------
__device__ void anchor_unit(int bid0, const float* __restrict__ mainp,
                            const float* __restrict__ emap,
                            float sdot[16][65], int* sslot) {
    const int t = threadIdx.x;
    const int chalf = bid0 >> 9;
    const int bid = bid0 & 511;
    const int b = bid >> 6, y = bid & 63;
    const int j = y >> 3, yin = y & 7;
    __syncthreads();
    if (t < 8) sslot[t] = g_slot[b * 64 + j * 8 + t];
    __syncthreads();

    const int g = t & 15, r = t >> 4;
    const int kslot = g >> 1;
    const unsigned xh = (unsigned)(g & 1);
    const size_t base4 = ((size_t)b * 256 * 64 + y) * 16 + g;
    const float4* mp = (const float4*)mainp;
    const float4* ep = (const float4*)emap;
    uint2* Aout = (uint2*)g_A;

    float d0 = 0.f, d1 = 0.f, d2 = 0.f, d3 = 0.f;
#pragma unroll
    for (int it = 0; it < 8; ++it) {
        const int c = r + 16 * it + chalf * 128;
        const size_t o = base4 + (size_t)c * 1024;
        const float4 mv = mp[o];
        const float4 ev = ep[o];
        d0 += mv.x * ev.x; d1 += mv.y * ev.y; d2 += mv.z * ev.z; d3 += mv.w * ev.w;
        const __half2 lo = __floats2half2_rn(mv.x * SCALEF, mv.y * SCALEF);
        const __half2 hi = __floats2half2_rn(mv.z * SCALEF, mv.w * SCALEF);
        uint2 v;
        v.x = *(const unsigned*)&lo;
        v.y = *(const unsigned*)&hi;
        Aout[(size_t)((sslot[kslot] * 8 + yin) * 256 + c) * 2 + xh] = v;
    }
    sdot[r][4 * g + 0] = d0; sdot[r][4 * g + 1] = d1;
    sdot[r][4 * g + 2] = d2; sdot[r][4 * g + 3] = d3;
    __syncthreads();
    if (t < 64) {
        float dd = 0.f;
#pragma unroll
        for (int i = 0; i < 16; ++i) dd += sdot[i][t];
        atomicAdd(&g_pos_sim[sslot[t >> 3] * 64 + yin * 8 + (t & 7)], dd * SCALEF);
    }
    __threadfence();
    __syncthreads();
    if (t == 0) atomicAdd(&g_grpcnt[b * 8 + j], 1);
}

// ---------------------------------------------------------------------------
// 3) fused persistent kernel. grid 148, block 256.
//    CTAs < NPROD: drain conversion queue, then join GEMM queue.
//    GEMM: 2M x 4N warp tiling, bulk-copy double buffering, spin-wait deps.
// ---------------------------------------------------------------------------
#define SMEM_DYN (3 * TILEB)

__global__ __launch_bounds__(256, 1) void fused_kernel(const float* __restrict__ mainp,
                                                       const float* __restrict__ emap,
                                                       const float* __restrict__ neg,
                                                       const float* __restrict__ pos) {
    extern __shared__ __align__(128) unsigned char dsm[];
    __shared__ __align__(8) unsigned long long s_mbar[2];
    __shared__ float sh_m[3][128], sh_s[3][128];
    __shared__ float s_dot[16][65];
    __shared__ int s_slot[8];
    __shared__ int s_unit;

    const int t = threadIdx.x, w = t >> 5, lane = t & 31;
    const unsigned sA_u = sm2u(dsm);
    const unsigned sB_u[2] = { sA_u + TILEB, sA_u + 2 * TILEB };
    const unsigned mb[2] = { sm2u(&s_mbar[0]), sm2u(&s_mbar[1]) };

    // ---- producer phase ----
    if (blockIdx.x < NPROD) {
        for (;;) {
            if (t == 0) s_unit = atomicAdd(&g_ctr_conv, 1);
            __syncthreads();
            const int u = s_unit;
            if (u >= NCONV) break;
            if (u < 64) bank_unit(u, neg, pos, (char*)dsm);
            else anchor_unit(u - 64, mainp, emap, s_dot, s_slot);
            __syncthreads();
        }
    }

    // ---- consumer phase ----
    if (t == 0) {
        asm volatile("mbarrier.init.shared.b64 [%0], 1;" :: "r"(mb[0]) : "memory");
        asm volatile("mbarrier.init.shared.b64 [%0], 1;" :: "r"(mb[1]) : "memory");
    }
    __syncthreads();

    const int mw = w & 1, nw = w >> 1;            // 2 M-halves x 4 N-quarters
    const unsigned a_lane = (unsigned)(((lane >> 3) & 1) * 4096 +
                                       ((lane & 7) + 8 * (lane >> 4)) * 16);
    const unsigned a_base0 = sA_u + (unsigned)(mw * 32768) + a_lane;
    const int row_b = (lane & 7) + 8 * ((lane >> 4) & 1);
    const int kc = (lane >> 3) & 1;
    const int rl = row_b & 7;

    const char* negc = (const char*)g_negB;
    const char* posc = (const char*)g_posB;

    unsigned ph[2] = {0u, 0u};

    for (;;) {
        if (t == 0) s_unit = atomicAdd(&g_ctr, 1);
        __syncthreads();
        const int u = s_unit;
        if (u >= NUNITS) break;
        const int q = u >> 2, quarter = u & 3;

        const int info = g_pairinfo[q];
        const int f0 = info & 1, f1 = (info >> 1) & 1;
        const int mixed = (f0 != f1);
        const int nch = mixed ? 8 : 4;
        const int shift = mixed ? 2 : 8;

        auto bsrc = [&](int cc) -> const char* {
            const int f = mixed ? ((cc >> 2) ? f1 : f0) : f0;
            const int tile = quarter * 4 + (cc & 3);
            return (f ? posc : negc) + (size_t)tile * TILEB;
        };

        if (t == 0) {
            // ---- spin-wait on producers ----
            const int gr0 = g_sgrp[2 * q], gr1 = g_sgrp[2 * q + 1];
            while (*(volatile int*)&g_grpcnt[gr0] < 16) {}
            while (*(volatile int*)&g_grpcnt[gr1] < 16) {}
#pragma unroll
            for (int cc2 = 0; cc2 < 4; ++cc2) {
                const int tile = quarter * 4 + cc2;
                while (*(volatile int*)&g_bankcnt[f0 * 16 + tile] < 2) {}
                if (mixed) while (*(volatile int*)&g_bankcnt[f1 * 16 + tile] < 2) {}
            }
            mbar_expect(mb[0], 2 * TILEB);
            bulk_copy(sA_u, (const char*)g_A + (size_t)q * TILEB, TILEB, mb[0]);
            bulk_copy(sB_u[0], bsrc(0), TILEB, mb[0]);
            mbar_expect(mb[1], TILEB);
            bulk_copy(sB_u[1], bsrc(1), TILEB, mb[1]);
        }

        float m_st[8], s_st[8];
#pragma unroll
        for (int i = 0; i < 8; ++i) { m_st[i] = NEG_HUGE; s_st[i] = 0.f; }

        for (int cc = 0; cc < nch; ++cc) {
            const int buf = cc & 1;
            mbar_wait(mb[buf], ph[buf]);
            ph[buf] ^= 1u;

            const bool active = !mixed || (mw == (cc >> shift));
            if (active) {
                unsigned acc[4][2][2][2];
#pragma unroll
                for (int f = 0; f < 4; ++f)
#pragma unroll
                    for (int nt = 0; nt < 2; ++nt)
#pragma unroll
                        for (int p = 0; p < 2; ++p) {
                            acc[f][nt][p][0] = 0u; acc[f][nt][p][1] = 0u;
                        }
                const unsigned brow0 = sB_u[buf] + (unsigned)((nw * 32 + row_b) * 512);
                const unsigned brow1 = brow0 + 16u * 512u;
#pragma unroll
                for (int ks = 0; ks < 16; ++ks) {
                    unsigned a[4][4];
#pragma unroll
                    for (int f = 0; f < 4; ++f)
                        ldsm4t(a[f][0], a[f][1], a[f][2], a[f][3],
                               a_base0 + (unsigned)(f * 8192 + ks * 256));
                    const int c = 2 * ks + kc;
                    const unsigned coff = (unsigned)(((c & 24) | ((c & 7) ^ rl)) * 16);
#pragma unroll
                    for (int nt = 0; nt < 2; ++nt) {
                        unsigned b0, b1, b2, b3;
                        ldsm4(b0, b1, b2, b3, (nt ? brow1 : brow0) + coff);
#pragma unroll
                        for (int f = 0; f < 4; ++f) {
                            mma_f16(acc[f][nt][0][0], acc[f][nt][0][1],
                                    a[f][0], a[f][1], a[f][2], a[f][3], b0, b1);
                            mma_f16(acc[f][nt][1][0], acc[f][nt][1][1],
                                    a[f][0], a[f][1], a[f][2], a[f][3], b2, b3);
                        }
                    }
                }
#pragma unroll
                for (int idx = 0; idx < 8; ++idx) {
                    const int f = idx >> 1, h = idx & 1;
                    __half2 mx2 = u2h2(acc[f][0][0][h]);
                    mx2 = __hmax2(mx2, u2h2(acc[f][0][1][h]));
                    mx2 = __hmax2(mx2, u2h2(acc[f][1][0][h]));
                    mx2 = __hmax2(mx2, u2h2(acc[f][1][1][h]));
                    float mx = fmaxf(__low2float(mx2), __high2float(mx2));
                    mx = fmaxf(mx, __shfl_xor_sync(~0u, mx, 1));
                    mx = fmaxf(mx, __shfl_xor_sync(~0u, mx, 2));
                    const float nm = fmaxf(m_st[idx], mx);
                    const __half2 nm2 = __float2half2_rn(nm);
                    __half2 s2a = h2ex2(__hsub2(u2h2(acc[f][0][0][h]), nm2));
                    __half2 s2b = h2ex2(__hsub2(u2h2(acc[f][0][1][h]), nm2));
                    s2a = __hadd2(s2a, h2ex2(__hsub2(u2h2(acc[f][1][0][h]), nm2)));
                    s2b = __hadd2(s2b, h2ex2(__hsub2(u2h2(acc[f][1][1][h]), nm2)));
                    const __half2 s2 = __hadd2(s2a, s2b);
                    float su = __low2float(s2) + __high2float(s2);
                    su += __shfl_xor_sync(~0u, su, 1);
                    su += __shfl_xor_sync(~0u, su, 2);
                    s_st[idx] = s_st[idx] * ex2f(m_st[idx] - nm) + su;
                    m_st[idx] = nm;
                }
            }
            __syncthreads();
            if (cc + 2 < nch && t == 0) {
                mbar_expect(mb[buf], TILEB);
                bulk_copy(sB_u[buf], bsrc(cc + 2), TILEB, mb[buf]);
            }
        }

        // combine 4 N-quarter warps per row -> write partial (M,S)
        if (nw > 0 && (lane & 3) == 0) {
#pragma unroll
            for (int idx = 0; idx < 8; ++idx) {
                const int row = mw * 64 + (idx >> 1) * 16 + (lane >> 2) + 8 * (idx & 1);
                sh_m[nw - 1][row] = m_st[idx];
                sh_s[nw - 1][row] = s_st[idx];
            }
        }
        __syncthreads();
        if (nw == 0 && (lane & 3) == 0) {
#pragma unroll
            for (int idx = 0; idx < 8; ++idx) {
                const int row = mw * 64 + (idx >> 1) * 16 + (lane >> 2) + 8 * (idx & 1);
                float M = m_st[idx], S = s_st[idx];
#pragma unroll
                for (int v = 0; v < 3; ++v) {
                    const float m2 = sh_m[v][row], s2 = sh_s[v][row];
                    const float NM = fmaxf(M, m2);
                    S = S * ex2f(M - NM) + s2 * ex2f(m2 - NM);
                    M = NM;
                }
                g_pms[u * 128 + row] = make_float2(M, S);
            }
        }
        __syncthreads();
    }
}

// ---------------------------------------------------------------------------
// 4) merge 4 quarter-partials per row -> loss; block partial sums
// ---------------------------------------------------------------------------
__global__ void merge_kernel() {
    __shared__ float sred[8];
    const int t = threadIdx.x, blk = blockIdx.x;
    const int r = blk * 256 + t;
    const int q = r >> 7, row = r & 127;
    float M = NEG_HUGE, S = 0.f;
#pragma unroll
    for (int quarter = 0; quarter < 4; ++quarter) {
        const float2 ms = g_pms[((q * 4 + quarter) * 128) + row];
        const float NM = fmaxf(M, ms.x);
        S = S * ex2f(M - NM) + ms.y * ex2f(ms.x - NM);
        M = NM;
    }
    const float p = g_pos_sim[r];
    const float mf = fmaxf(M, p);
    const float ep = ex2f(p - mf);
    const float denom = S * ex2f(M - mf) + ep + EPSV;
    float loss = -logf(ep / denom + EPSV);
#pragma unroll
    for (int o = 16; o; o >>= 1) loss += __shfl_xor_sync(~0u, loss, o);
    if ((t & 31) == 0) sred[t >> 5] = loss;
    __syncthreads();
    if (t == 0) {
        float tot = 0.f;
#pragma unroll
        for (int i = 0; i < 8; ++i) tot += sred[i];
        g_part[blk] = tot;
    }
}

// ---------------------------------------------------------------------------
// 5) final reduction (128 partials)
// ---------------------------------------------------------------------------
__global__ void finalize_kernel(float* __restrict__ out) {
    __shared__ float sred[4];
    const int t = threadIdx.x;
    float v = g_part[t];
#pragma unroll
    for (int o = 16; o; o >>= 1) v += __shfl_xor_sync(~0u, v, o);
    if ((t & 31) == 0) sred[t >> 5] = v;
    __syncthreads();
    if (t == 0) {
        float tot = sred[0] + sred[1] + sred[2] + sred[3];
        out[0] = tot * (1.f / 32768.f);
    }
}

// ---------------------------------------------------------------------------
extern "C" void kernel_launch(void* const* d_in, const int* in_sizes, int n_in,
                              void* d_out, int out_size) {
    const float* mainp = (const float*)d_in[0];
    const float* emap  = (const float*)d_in[1];
    const float* lab   = (const float*)d_in[2];
    const float* neg   = (const float*)d_in[3];
    const float* pos   = (const float*)d_in[4];
    float* out = (float*)d_out;

    cudaFuncSetAttribute(fused_kernel,
                         cudaFuncAttributeMaxDynamicSharedMemorySize, SMEM_DYN);

    label_kernel<<<NPATCH, 256>>>(lab);
    perm_kernel<<<1, 512>>>();
    fused_kernel<<<148, 256, SMEM_DYN>>>(mainp, emap, neg, pos);
    merge_kernel<<<128, 256>>>();
    finalize_kernel<<<1, 128>>>(out);
}

// round 14
// speedup vs baseline: 1.0898x; 1.0898x over previous
#include <cuda_runtime.h>
#include <cuda_fp16.h>
#include <cstdint>

// ---------------------------------------------------------------------------
// ContrastivePatchLoss — fused persistent kernel, group-major producer order.
// Producer CTAs convert banks+anchors (queue: 64 bank units, then 1024 anchor
// units ordered so each anchor group (b,j) completes contiguously); consumer
// CTAs run HMMA f16-acc GEMM+softmax with spin-wait deps, then producers join.
// ---------------------------------------------------------------------------

#define NPATCH   512
#define ROWS_TOT 32768
#define NBANK    2048
#define EPSV     1e-5f
#define SCALEF   2.8853900817779268f   // (1/0.5) * log2(e)
#define NEG_HUGE (-1e30f)
#define TILEB    65536                 // 128 rows x 512 B
#define NUNITS   1024                  // 256 q x 4 col-quarters
#define NCONV    1088                  // 64 bank units + 1024 anchor units
#define NPROD    64                    // producer CTAs

// g_A blocked: [slot(512)][yin(8)][c(256)][xin(8)] fp16
__device__ __half g_A[ROWS_TOT * 256];
// banks pre-swizzled: [tile(16)][row(128)][c'(32) x 16B], c' = (c&24)|((c^row)&7)
__device__ __half g_negB[NBANK * 256];
__device__ __half g_posB[NBANK * 256];
__device__ float g_pos_sim[ROWS_TOT];
__device__ int   g_flags[NPATCH];
__device__ int   g_slot[NPATCH];
__device__ int   g_sgrp[NPATCH];                  // slot -> group (b*8+j)
__device__ int   g_pairinfo[256];
__device__ int   g_ctr;                           // GEMM unit queue
__device__ int   g_ctr_conv;                      // conversion unit queue
__device__ int   g_grpcnt[64];                    // anchor group counters (->16)
__device__ int   g_bankcnt[32];                   // bank tile counters (->2)
__device__ float2 g_pms[NUNITS * 128];            // per-(unit,row) partial (M,S)
__device__ float g_part[128];

// ---------------------------------------------------------------------------
__device__ __forceinline__ unsigned sm2u(const void* p) {
    return (unsigned)__cvta_generic_to_shared(p);
}
__device__ __forceinline__ float ex2f(float x) {
    float y; asm("ex2.approx.f32 %0, %1;" : "=f"(y) : "f"(x)); return y;
}
__device__ __forceinline__ __half2 h2ex2(__half2 x) {
    __half2 y;
    asm("ex2.approx.f16x2 %0, %1;" : "=r"(*(unsigned*)&y) : "r"(*(unsigned*)&x));
    return y;
}
__device__ __forceinline__ __half2 u2h2(unsigned u) { return *(__half2*)&u; }
__device__ __forceinline__ void ldsm4(unsigned& r0, unsigned& r1, unsigned& r2, unsigned& r3,
                                      unsigned addr) {
    asm volatile("ldmatrix.sync.aligned.m8n8.x4.shared.b16 {%0,%1,%2,%3}, [%4];\n"
                 : "=r"(r0), "=r"(r1), "=r"(r2), "=r"(r3) : "r"(addr));
}
__device__ __forceinline__ void ldsm4t(unsigned& r0, unsigned& r1, unsigned& r2, unsigned& r3,
                                       unsigned addr) {
    asm volatile("ldmatrix.sync.aligned.m8n8.x4.trans.shared.b16 {%0,%1,%2,%3}, [%4];\n"
                 : "=r"(r0), "=r"(r1), "=r"(r2), "=r"(r3) : "r"(addr));
}
__device__ __forceinline__ void mma_f16(unsigned& c0, unsigned& c1,
                                        unsigned a0, unsigned a1, unsigned a2, unsigned a3,
                                        unsigned b0, unsigned b1) {
    asm volatile("mma.sync.aligned.m16n8k16.row.col.f16.f16.f16.f16 "
                 "{%0,%1},{%2,%3,%4,%5},{%6,%7},{%0,%1};\n"
                 : "+r"(c0), "+r"(c1)
                 : "r"(a0), "r"(a1), "r"(a2), "r"(a3), "r"(b0), "r"(b1));
}
__device__ __forceinline__ void mbar_wait(unsigned addr, unsigned parity) {
    asm volatile("{\n\t.reg .pred P;\n"
                 "W%=:\n\tmbarrier.try_wait.parity.shared.b64 P, [%0], %1;\n"
                 "\t@P bra D%=;\n\tbra W%=;\nD%=:\n\t}"
                 :: "r"(addr), "r"(parity) : "memory");
}
__device__ __forceinline__ void mbar_expect(unsigned addr, unsigned bytes) {
    asm volatile("mbarrier.arrive.expect_tx.shared.b64 _, [%0], %1;"
                 :: "r"(addr), "r"(bytes) : "memory");
}
__device__ __forceinline__ void bulk_copy(unsigned dst, const void* src, unsigned bytes,
                                          unsigned mbar) {
    asm volatile("cp.async.bulk.shared::cluster.global.mbarrier::complete_tx::bytes "
                 "[%0], [%1], %2, [%3];"
                 :: "r"(dst), "l"(src), "r"(bytes), "r"(mbar) : "memory");
}

// ---------------------------------------------------------------------------
// 1) label patch means -> flags; also zeroes g_pos_sim for the atomic combine
// ---------------------------------------------------------------------------
__global__ void label_kernel(const float* __restrict__ lab) {
    __shared__ float sred[8];
    const int p = blockIdx.x, t = threadIdx.x;
    if (t < 64) g_pos_sim[p * 64 + t] = 0.f;
    const int b = p >> 6, j = (p >> 3) & 7, k = p & 7;
    const float* base = lab + (size_t)b * 65536 + (size_t)j * 32 * 256 + k * 32;
    float sum = 0.f;
#pragma unroll
    for (int it = 0; it < 4; ++it) {
        int u = t + 256 * it;
        int y = u >> 5, x = u & 31;
        sum += base[y * 256 + x];
    }
#pragma unroll
    for (int o = 16; o; o >>= 1) sum += __shfl_xor_sync(~0u, sum, o);
    if ((t & 31) == 0) sred[t >> 5] = sum;
    __syncthreads();
    if (t == 0) {
        float s2 = 0.f;
#pragma unroll
        for (int i = 0; i < 8; ++i) s2 += sred[i];
        g_flags[p] = (s2 * (1.f / 1024.f) < 0.1f) ? 1 : 0;
    }
}

// ---------------------------------------------------------------------------
// 2) permutation + all counter resets + slot->group map
// ---------------------------------------------------------------------------
__global__ void perm_kernel() {
    __shared__ int sc[512], sflag[512];
    const int t = threadIdx.x;
    if (t == 0) { g_ctr = 0; g_ctr_conv = 0; }
    if (t < 64) g_grpcnt[t] = 0;
    if (t < 32) g_bankcnt[t] = 0;
    const int f = g_flags[t];
    sc[t] = f;
    __syncthreads();
    for (int off = 1; off < 512; off <<= 1) {
        int add = (t >= off) ? sc[t - off] : 0;
        __syncthreads();
        sc[t] += add;
        __syncthreads();
    }
    const int npos = sc[511];
    const int slot = f ? (sc[t] - 1) : (npos + t - sc[t]);
    g_slot[t] = slot;
    g_sgrp[slot] = t >> 3;                        // group = b*8+j
    sflag[slot] = f;
    __syncthreads();
    if (t < 256) g_pairinfo[t] = sflag[2 * t] | (sflag[2 * t + 1] << 1);
}

// ---------------------------------------------------------------------------
// producer unit: bank conversion (u in [0,64))
// ---------------------------------------------------------------------------
__device__ void bank_unit(int u, const float* __restrict__ neg,
                          const float* __restrict__ pos, char* stage) {
    __half (*sT)[66] = (__half(*)[66])stage;
    const int t = threadIdx.x;
    const int bank = u >> 5, l = u & 31;
    const float* src = (bank ? pos : neg) + (size_t)l * 16384;
    __syncthreads();
#pragma unroll 4
    for (int it = 0; it < 64; ++it) {
        int u2 = t + 256 * it;
        int c = u2 >> 6, s = u2 & 63;
        sT[c][s] = __float2half(src[c * 64 + s]);
    }
    __syncthreads();
    unsigned* dst32 = (unsigned*)((bank ? g_posB : g_negB));
    const int tile = l >> 1;
    const int rbase = (l & 1) * 64;
#pragma unroll 4
    for (int it = 0; it < 32; ++it) {
        int u2 = t + 256 * it;
        int s = u2 >> 7, cc = u2 & 127;
        unsigned lo = __half_as_ushort(sT[2 * cc][s]);
        unsigned hi = __half_as_ushort(sT[2 * cc + 1][s]);
        const int row = rbase + s;
        const int c16 = cc >> 2;
        const int csw = (c16 & 24) | ((c16 ^ row) & 7);
        dst32[(tile * 65536 + row * 512 + csw * 16 + (cc & 3) * 4) >> 2] = (hi << 16) | lo;
    }
    __threadfence();
    __syncthreads();
    if (t == 0) atomicAdd(&g_bankcnt[bank * 16 + tile], 1);
}

// ---------------------------------------------------------------------------
// producer unit: anchor conversion for (b, y, chalf) — R11 layout
// ---------------------------------------------------------------------------
__device__ void anchor_unit(int b, int y, int chalf, const float* __restrict__ mainp,
                            const float* __restrict__ emap,
                            float sdot[16][65], int* sslot) {
    const int t = threadIdx.x;
    const int j = y >> 3, yin = y & 7;
    __syncthreads();
    if (t < 8) sslot[t] = g_slot[b * 64 + j * 8 + t];
    __syncthreads();

    const int g = t & 15, r = t >> 4;
    const int kslot = g >> 1;
    const unsigned xh = (unsigned)(g & 1);
    const size_t base4 = ((size_t)b * 256 * 64 + y) * 16 + g;
    const float4* mp = (const float4*)mainp;
    const float4* ep = (const float4*)emap;
    uint2* Aout = (uint2*)g_A;

    float d0 = 0.f, d1 = 0.f, d2 = 0.f, d3 = 0.f;
#pragma unroll
    for (int it = 0; it < 8; ++it) {
        const int c = r + 16 * it + chalf * 128;
        const size_t o = base4 + (size_t)c * 1024;
        const float4 mv = mp[o];
        const float4 ev = ep[o];
        d0 += mv.x * ev.x; d1 += mv.y * ev.y; d2 += mv.z * ev.z; d3 += mv.w * ev.w;
        const __half2 lo = __floats2half2_rn(mv.x * SCALEF, mv.y * SCALEF);
        const __half2 hi = __floats2half2_rn(mv.z * SCALEF, mv.w * SCALEF);
        uint2 v;
        v.x = *(const unsigned*)&lo;
        v.y = *(const unsigned*)&hi;
        Aout[(size_t)((sslot[kslot] * 8 + yin) * 256 + c) * 2 + xh] = v;
    }
    sdot[r][4 * g + 0] = d0; sdot[r][4 * g + 1] = d1;
    sdot[r][4 * g + 2] = d2; sdot[r][4 * g + 3] = d3;
    __syncthreads();
    if (t < 64) {
        float dd = 0.f;
#pragma unroll
        for (int i = 0; i < 16; ++i) dd += sdot[i][t];
        atomicAdd(&g_pos_sim[sslot[t >> 3] * 64 + yin * 8 + (t & 7)], dd * SCALEF);
    }
    __threadfence();
    __syncthreads();
    if (t == 0) atomicAdd(&g_grpcnt[b * 8 + j], 1);
}

// ---------------------------------------------------------------------------
// 3) fused persistent kernel. grid 148, block 256.
//    CTAs < NPROD drain the conversion queue (banks first, anchors group-major)
//    then join the GEMM queue; others start GEMM immediately with spin-waits.
// ---------------------------------------------------------------------------
#define SMEM_DYN (3 * TILEB)

__global__ __launch_bounds__(256, 1) void fused_kernel(const float* __restrict__ mainp,
                                                       const float* __restrict__ emap,
                                                       const float* __restrict__ neg,
                                                       const float* __restrict__ pos) {
    extern __shared__ __align__(128) unsigned char dsm[];
    __shared__ __align__(8) unsigned long long s_mbar[2];
    __shared__ float sh_m[3][128], sh_s[3][128];
    __shared__ float s_dot[16][65];
    __shared__ int s_slot[8];
    __shared__ int s_unit;

    const int t = threadIdx.x, w = t >> 5, lane = t & 31;
    const unsigned sA_u = sm2u(dsm);
    const unsigned sB_u[2] = { sA_u + TILEB, sA_u + 2 * TILEB };
    const unsigned mb[2] = { sm2u(&s_mbar[0]), sm2u(&s_mbar[1]) };

    // ---- producer phase ----
    if (blockIdx.x < NPROD) {
        for (;;) {
            if (t == 0) s_unit = atomicAdd(&g_ctr_conv, 1);
            __syncthreads();
            const int u = s_unit;
            if (u >= NCONV) break;
            if (u < 64) {
                bank_unit(u, neg, pos, (char*)dsm);
            } else {
                // group-major: g = (u-64)>>4, sub = (u-64)&15 -> (yin, chalf)
                const int u2 = u - 64;
                const int g = u2 >> 4, sub = u2 & 15;
                const int b = g >> 3, j = g & 7;
                const int yin = sub >> 1, chalf = sub & 1;
                anchor_unit(b, j * 8 + yin, chalf, mainp, emap, s_dot, s_slot);
            }
            __syncthreads();
        }
    }

    // ---- consumer phase ----
    if (t == 0) {
        asm volatile("mbarrier.init.shared.b64 [%0], 1;" :: "r"(mb[0]) : "memory");
        asm volatile("mbarrier.init.shared.b64 [%0], 1;" :: "r"(mb[1]) : "memory");
    }
    __syncthreads();

    const int mw = w & 1, nw = w >> 1;            // 2 M-halves x 4 N-quarters
    const unsigned a_lane = (unsigned)(((lane >> 3) & 1) * 4096 +
                                       ((lane & 7) + 8 * (lane >> 4)) * 16);
    const unsigned a_base0 = sA_u + (unsigned)(mw * 32768) + a_lane;
    const int row_b = (lane & 7) + 8 * ((lane >> 4) & 1);
    const int kc = (lane >> 3) & 1;
    const int rl = row_b & 7;

    const char* negc = (const char*)g_negB;
    const char* posc = (const char*)g_posB;

    unsigned ph[2] = {0u, 0u};

    for (;;) {
        if (t == 0) s_unit = atomicAdd(&g_ctr, 1);
        __syncthreads();
        const int u = s_unit;
        if (u >= NUNITS) break;
        const int q = u >> 2, quarter = u & 3;

        const int info = g_pairinfo[q];
        const int f0 = info & 1, f1 = (info >> 1) & 1;
        const int mixed = (f0 != f1);
        const int nch = mixed ? 8 : 4;
        const int shift = mixed ? 2 : 8;

        auto bsrc = [&](int cc) -> const char* {
            const int f = mixed ? ((cc >> 2) ? f1 : f0) : f0;
            const int tile = quarter * 4 + (cc & 3);
            return (f ? posc : negc) + (size_t)tile * TILEB;
        };

        if (t == 0) {
            // ---- spin-wait on producers ----
            const int gr0 = g_sgrp[2 * q], gr1 = g_sgrp[2 * q + 1];
            while (*(volatile int*)&g_grpcnt[gr0] < 16) {}
            while (*(volatile int*)&g_grpcnt[gr1] < 16) {}
#pragma unroll
            for (int cc2 = 0; cc2 < 4; ++cc2) {
                const int tile = quarter * 4 + cc2;
                while (*(volatile int*)&g_bankcnt[f0 * 16 + tile] < 2) {}
                if (mixed) while (*(volatile int*)&g_bankcnt[f1 * 16 + tile] < 2) {}
            }
            mbar_expect(mb[0], 2 * TILEB);
            bulk_copy(sA_u, (const char*)g_A + (size_t)q * TILEB, TILEB, mb[0]);
            bulk_copy(sB_u[0], bsrc(0), TILEB, mb[0]);
            mbar_expect(mb[1], TILEB);
            bulk_copy(sB_u[1], bsrc(1), TILEB, mb[1]);
        }

        float m_st[8], s_st[8];
#pragma unroll
        for (int i = 0; i < 8; ++i) { m_st[i] = NEG_HUGE; s_st[i] = 0.f; }

        for (int cc = 0; cc < nch; ++cc) {
            const int buf = cc & 1;
            mbar_wait(mb[buf], ph[buf]);
            ph[buf] ^= 1u;

            const bool active = !mixed || (mw == (cc >> shift));
            if (active) {
                unsigned acc[4][2][2][2];
#pragma unroll
                for (int f = 0; f < 4; ++f)
#pragma unroll
                    for (int nt = 0; nt < 2; ++nt)
#pragma unroll
                        for (int p = 0; p < 2; ++p) {
                            acc[f][nt][p][0] = 0u; acc[f][nt][p][1] = 0u;
                        }
                const unsigned brow0 = sB_u[buf] + (unsigned)((nw * 32 + row_b) * 512);
                const unsigned brow1 = brow0 + 16u * 512u;
#pragma unroll
                for (int ks = 0; ks < 16; ++ks) {
                    unsigned a[4][4];
#pragma unroll
                    for (int f = 0; f < 4; ++f)
                        ldsm4t(a[f][0], a[f][1], a[f][2], a[f][3],
                               a_base0 + (unsigned)(f * 8192 + ks * 256));
                    const int c = 2 * ks + kc;
                    const unsigned coff = (unsigned)(((c & 24) | ((c & 7) ^ rl)) * 16);
#pragma unroll
                    for (int nt = 0; nt < 2; ++nt) {
                        unsigned b0, b1, b2, b3;
                        ldsm4(b0, b1, b2, b3, (nt ? brow1 : brow0) + coff);
#pragma unroll
                        for (int f = 0; f < 4; ++f) {
                            mma_f16(acc[f][nt][0][0], acc[f][nt][0][1],
                                    a[f][0], a[f][1], a[f][2], a[f][3], b0, b1);
                            mma_f16(acc[f][nt][1][0], acc[f][nt][1][1],
                                    a[f][0], a[f][1], a[f][2], a[f][3], b2, b3);
                        }
                    }
                }
#pragma unroll
                for (int idx = 0; idx < 8; ++idx) {
                    const int f = idx >> 1, h = idx & 1;
                    __half2 mx2 = u2h2(acc[f][0][0][h]);
                    mx2 = __hmax2(mx2, u2h2(acc[f][0][1][h]));
                    mx2 = __hmax2(mx2, u2h2(acc[f][1][0][h]));
                    mx2 = __hmax2(mx2, u2h2(acc[f][1][1][h]));
                    float mx = fmaxf(__low2float(mx2), __high2float(mx2));
                    mx = fmaxf(mx, __shfl_xor_sync(~0u, mx, 1));
                    mx = fmaxf(mx, __shfl_xor_sync(~0u, mx, 2));
                    const float nm = fmaxf(m_st[idx], mx);
                    const __half2 nm2 = __float2half2_rn(nm);
                    __half2 s2a = h2ex2(__hsub2(u2h2(acc[f][0][0][h]), nm2));
                    __half2 s2b = h2ex2(__hsub2(u2h2(acc[f][0][1][h]), nm2));
                    s2a = __hadd2(s2a, h2ex2(__hsub2(u2h2(acc[f][1][0][h]), nm2)));
                    s2b = __hadd2(s2b, h2ex2(__hsub2(u2h2(acc[f][1][1][h]), nm2)));
                    const __half2 s2 = __hadd2(s2a, s2b);
                    float su = __low2float(s2) + __high2float(s2);
                    su += __shfl_xor_sync(~0u, su, 1);
                    su += __shfl_xor_sync(~0u, su, 2);
                    s_st[idx] = s_st[idx] * ex2f(m_st[idx] - nm) + su;
                    m_st[idx] = nm;
                }
            }
            __syncthreads();
            if (cc + 2 < nch && t == 0) {
                mbar_expect(mb[buf], TILEB);
                bulk_copy(sB_u[buf], bsrc(cc + 2), TILEB, mb[buf]);
            }
        }

        // combine 4 N-quarter warps per row -> write partial (M,S)
        if (nw > 0 && (lane & 3) == 0) {
#pragma unroll
            for (int idx = 0; idx < 8; ++idx) {
                const int row = mw * 64 + (idx >> 1) * 16 + (lane >> 2) + 8 * (idx & 1);
                sh_m[nw - 1][row] = m_st[idx];
                sh_s[nw - 1][row] = s_st[idx];
            }
        }
        __syncthreads();
        if (nw == 0 && (lane & 3) == 0) {
#pragma unroll
            for (int idx = 0; idx < 8; ++idx) {
                const int row = mw * 64 + (idx >> 1) * 16 + (lane >> 2) + 8 * (idx & 1);
                float M = m_st[idx], S = s_st[idx];
#pragma unroll
                for (int v = 0; v < 3; ++v) {
                    const float m2 = sh_m[v][row], s2 = sh_s[v][row];
                    const float NM = fmaxf(M, m2);
                    S = S * ex2f(M - NM) + s2 * ex2f(m2 - NM);
                    M = NM;
                }
                g_pms[u * 128 + row] = make_float2(M, S);
            }
        }
        __syncthreads();
    }
}

// ---------------------------------------------------------------------------
// 4) merge 4 quarter-partials per row -> loss; block partial sums
// ---------------------------------------------------------------------------
__global__ void merge_kernel() {
    __shared__ float sred[8];
    const int t = threadIdx.x, blk = blockIdx.x;
    const int r = blk * 256 + t;
    const int q = r >> 7, row = r & 127;
    float M = NEG_HUGE, S = 0.f;
#pragma unroll
    for (int quarter = 0; quarter < 4; ++quarter) {
        const float2 ms = g_pms[((q * 4 + quarter) * 128) + row];
        const float NM = fmaxf(M, ms.x);
        S = S * ex2f(M - NM) + ms.y * ex2f(ms.x - NM);
        M = NM;
    }
    const float p = g_pos_sim[r];
    const float mf = fmaxf(M, p);
    const float ep = ex2f(p - mf);
    const float denom = S * ex2f(M - mf) + ep + EPSV;
    float loss = -logf(ep / denom + EPSV);
#pragma unroll
    for (int o = 16; o; o >>= 1) loss += __shfl_xor_sync(~0u, loss, o);
    if ((t & 31) == 0) sred[t >> 5] = loss;
    __syncthreads();
    if (t == 0) {
        float tot = 0.f;
#pragma unroll
        for (int i = 0; i < 8; ++i) tot += sred[i];
        g_part[blk] = tot;
    }
}

// ---------------------------------------------------------------------------
// 5) final reduction (128 partials)
// ---------------------------------------------------------------------------
__global__ void finalize_kernel(float* __restrict__ out) {
    __shared__ float sred[4];
    const int t = threadIdx.x;
    float v = g_part[t];
#pragma unroll
    for (int o = 16; o; o >>= 1) v += __shfl_xor_sync(~0u, v, o);
    if ((t & 31) == 0) sred[t >> 5] = v;
    __syncthreads();
    if (t == 0) {
        float tot = sred[0] + sred[1] + sred[2] + sred[3];
        out[0] = tot * (1.f / 32768.f);
    }
}

// ---------------------------------------------------------------------------
extern "C" void kernel_launch(void* const* d_in, const int* in_sizes, int n_in,
                              void* d_out, int out_size) {
    const float* mainp = (const float*)d_in[0];
    const float* emap  = (const float*)d_in[1];
    const float* lab   = (const float*)d_in[2];
    const float* neg   = (const float*)d_in[3];
    const float* pos   = (const float*)d_in[4];
    float* out = (float*)d_out;

    cudaFuncSetAttribute(fused_kernel,
                         cudaFuncAttributeMaxDynamicSharedMemorySize, SMEM_DYN);

    label_kernel<<<NPATCH, 256>>>(lab);
    perm_kernel<<<1, 512>>>();
    fused_kernel<<<148, 256, SMEM_DYN>>>(mainp, emap, neg, pos);
    merge_kernel<<<128, 256>>>();
    finalize_kernel<<<1, 128>>>(out);
}

// round 15
// speedup vs baseline: 1.2563x; 1.1528x over previous
#include <cuda_runtime.h>
#include <cuda_fp16.h>
#include <cstdint>

// ---------------------------------------------------------------------------
// ContrastivePatchLoss — persistent HMMA f16-acc GEMM (16 warps, 4Mx4N)
// + split softmax merge. Separate conversion kernels (R11 pipeline).
// ---------------------------------------------------------------------------

#define NPATCH   512
#define ROWS_TOT 32768
#define NBANK    2048
#define EPSV     1e-5f
#define SCALEF   2.8853900817779268f   // (1/0.5) * log2(e)
#define NEG_HUGE (-1e30f)
#define TILEB    65536                 // 128 rows x 512 B
#define NUNITS   1024                  // 256 q x 4 col-quarters

// g_A blocked: [slot(512)][yin(8)][c(256)][xin(8)] fp16
__device__ __half g_A[ROWS_TOT * 256];
// banks pre-swizzled: [tile(16)][row(128)][c'(32) x 16B], c' = (c&24)|((c^row)&7)
__device__ __half g_negB[NBANK * 256];
__device__ __half g_posB[NBANK * 256];
__device__ float g_pos_sim[ROWS_TOT];
__device__ int   g_flags[NPATCH];
__device__ int   g_slot[NPATCH];
__device__ int   g_pairinfo[256];
__device__ int   g_ctr;
__device__ float2 g_pms[NUNITS * 128];            // per-(unit,row) partial (M,S)
__device__ float g_part[128];

// ---------------------------------------------------------------------------
__device__ __forceinline__ unsigned sm2u(const void* p) {
    return (unsigned)__cvta_generic_to_shared(p);
}
__device__ __forceinline__ float ex2f(float x) {
    float y; asm("ex2.approx.f32 %0, %1;" : "=f"(y) : "f"(x)); return y;
}
__device__ __forceinline__ __half2 h2ex2(__half2 x) {
    __half2 y;
    asm("ex2.approx.f16x2 %0, %1;" : "=r"(*(unsigned*)&y) : "r"(*(unsigned*)&x));
    return y;
}
__device__ __forceinline__ __half2 u2h2(unsigned u) { return *(__half2*)&u; }
__device__ __forceinline__ void ldsm4(unsigned& r0, unsigned& r1, unsigned& r2, unsigned& r3,
                                      unsigned addr) {
    asm volatile("ldmatrix.sync.aligned.m8n8.x4.shared.b16 {%0,%1,%2,%3}, [%4];\n"
                 : "=r"(r0), "=r"(r1), "=r"(r2), "=r"(r3) : "r"(addr));
}
__device__ __forceinline__ void ldsm4t(unsigned& r0, unsigned& r1, unsigned& r2, unsigned& r3,
                                       unsigned addr) {
    asm volatile("ldmatrix.sync.aligned.m8n8.x4.trans.shared.b16 {%0,%1,%2,%3}, [%4];\n"
                 : "=r"(r0), "=r"(r1), "=r"(r2), "=r"(r3) : "r"(addr));
}
__device__ __forceinline__ void mma_f16(unsigned& c0, unsigned& c1,
                                        unsigned a0, unsigned a1, unsigned a2, unsigned a3,
                                        unsigned b0, unsigned b1) {
    asm volatile("mma.sync.aligned.m16n8k16.row.col.f16.f16.f16.f16 "
                 "{%0,%1},{%2,%3,%4,%5},{%6,%7},{%0,%1};\n"
                 : "+r"(c0), "+r"(c1)
                 : "r"(a0), "r"(a1), "r"(a2), "r"(a3), "r"(b0), "r"(b1));
}
__device__ __forceinline__ void mbar_wait(unsigned addr, unsigned parity) {
    asm volatile("{\n\t.reg .pred P;\n"
                 "W%=:\n\tmbarrier.try_wait.parity.shared.b64 P, [%0], %1;\n"
                 "\t@P bra D%=;\n\tbra W%=;\nD%=:\n\t}"
                 :: "r"(addr), "r"(parity) : "memory");
}
__device__ __forceinline__ void mbar_expect(unsigned addr, unsigned bytes) {
    asm volatile("mbarrier.arrive.expect_tx.shared.b64 _, [%0], %1;"
                 :: "r"(addr), "r"(bytes) : "memory");
}
__device__ __forceinline__ void bulk_copy(unsigned dst, const void* src, unsigned bytes,
                                          unsigned mbar) {
    asm volatile("cp.async.bulk.shared::cluster.global.mbarrier::complete_tx::bytes "
                 "[%0], [%1], %2, [%3];"
                 :: "r"(dst), "l"(src), "r"(bytes), "r"(mbar) : "memory");
}

// ---------------------------------------------------------------------------
// 1) label patch means -> flags; also zeroes g_pos_sim for the atomic combine
// ---------------------------------------------------------------------------
__global__ void label_kernel(const float* __restrict__ lab) {
    __shared__ float sred[8];
    const int p = blockIdx.x, t = threadIdx.x;
    if (t < 64) g_pos_sim[p * 64 + t] = 0.f;
    const int b = p >> 6, j = (p >> 3) & 7, k = p & 7;
    const float* base = lab + (size_t)b * 65536 + (size_t)j * 32 * 256 + k * 32;
    float sum = 0.f;
#pragma unroll
    for (int it = 0; it < 4; ++it) {
        int u = t + 256 * it;
        int y = u >> 5, x = u & 31;
        sum += base[y * 256 + x];
    }
#pragma unroll
    for (int o = 16; o; o >>= 1) sum += __shfl_xor_sync(~0u, sum, o);
    if ((t & 31) == 0) sred[t >> 5] = sum;
    __syncthreads();
    if (t == 0) {
        float s2 = 0.f;
#pragma unroll
        for (int i = 0; i < 8; ++i) s2 += sred[i];
        g_flags[p] = (s2 * (1.f / 1024.f) < 0.1f) ? 1 : 0;
    }
}

// ---------------------------------------------------------------------------
// 2) permutation + work-counter reset
// ---------------------------------------------------------------------------
__global__ void perm_kernel() {
    __shared__ int sc[512], sflag[512];
    const int t = threadIdx.x;
    if (t == 0) g_ctr = 0;
    const int f = g_flags[t];
    sc[t] = f;
    __syncthreads();
    for (int off = 1; off < 512; off <<= 1) {
        int add = (t >= off) ? sc[t - off] : 0;
        __syncthreads();
        sc[t] += add;
        __syncthreads();
    }
    const int npos = sc[511];
    const int slot = f ? (sc[t] - 1) : (npos + t - sc[t]);
    g_slot[t] = slot;
    sflag[slot] = f;
    __syncthreads();
    if (t < 256) g_pairinfo[t] = sflag[2 * t] | (sflag[2 * t + 1] << 1);
}

// ---------------------------------------------------------------------------
// 3) banks [32,256,8,8] f32 -> fp16, pre-swizzled tile layout
// ---------------------------------------------------------------------------
__global__ void convert_bank_kernel(const float* __restrict__ neg, const float* __restrict__ pos) {
    __shared__ __half sT[256][66];
    const int blk = blockIdx.x, t = threadIdx.x;
    const int bank = blk >> 5, l = blk & 31;
    const float* src = (bank ? pos : neg) + (size_t)l * 16384;
#pragma unroll 4
    for (int it = 0; it < 64; ++it) {
        int u = t + 256 * it;
        int c = u >> 6, s = u & 63;
        sT[c][s] = __float2half(src[c * 64 + s]);
    }
    __syncthreads();
    unsigned* dst32 = (unsigned*)((bank ? g_posB : g_negB));
    const int tile = l >> 1;
    const int rbase = (l & 1) * 64;
#pragma unroll 4
    for (int it = 0; it < 32; ++it) {
        int u = t + 256 * it;
        int s = u >> 7, cc = u & 127;
        unsigned lo = __half_as_ushort(sT[2 * cc][s]);
        unsigned hi = __half_as_ushort(sT[2 * cc + 1][s]);
        const int row = rbase + s;
        const int c16 = cc >> 2;
        const int csw = (c16 & 24) | ((c16 ^ row) & 7);
        dst32[(tile * 65536 + row * 512 + csw * 16 + (cc & 3) * 4) >> 2] = (hi << 16) | lo;
    }
}

// ---------------------------------------------------------------------------
// 4) anchors: grid 1024 = (chalf, b, y). Coalesced float4 reads, direct uint2
//    writes; pos dot halves combined via atomicAdd (deterministic 2-add).
// ---------------------------------------------------------------------------
__global__ void convert_anchor_kernel(const float* __restrict__ mainp,
                                      const float* __restrict__ emap) {
    __shared__ float sdot[16][65];
    __shared__ int sslot[8];
    const int bid0 = blockIdx.x, t = threadIdx.x;
    const int chalf = bid0 >> 9;
    const int bid = bid0 & 511;
    const int b = bid >> 6, y = bid & 63;
    const int j = y >> 3, yin = y & 7;
    if (t < 8) sslot[t] = g_slot[b * 64 + j * 8 + t];
    __syncthreads();

    const int g = t & 15, r = t >> 4;
    const int kslot = g >> 1;
    const unsigned xh = (unsigned)(g & 1);
    const size_t base4 = ((size_t)b * 256 * 64 + y) * 16 + g;
    const float4* mp = (const float4*)mainp;
    const float4* ep = (const float4*)emap;
    uint2* Aout = (uint2*)g_A;

    float d0 = 0.f, d1 = 0.f, d2 = 0.f, d3 = 0.f;
#pragma unroll
    for (int it = 0; it < 8; ++it) {
        const int c = r + 16 * it + chalf * 128;
        const size_t o = base4 + (size_t)c * 1024;
        const float4 mv = mp[o];
        const float4 ev = ep[o];
        d0 += mv.x * ev.x; d1 += mv.y * ev.y; d2 += mv.z * ev.z; d3 += mv.w * ev.w;
        const __half2 lo = __floats2half2_rn(mv.x * SCALEF, mv.y * SCALEF);
        const __half2 hi = __floats2half2_rn(mv.z * SCALEF, mv.w * SCALEF);
        uint2 v;
        v.x = *(const unsigned*)&lo;
        v.y = *(const unsigned*)&hi;
        Aout[(size_t)((sslot[kslot] * 8 + yin) * 256 + c) * 2 + xh] = v;
    }
    sdot[r][4 * g + 0] = d0; sdot[r][4 * g + 1] = d1;
    sdot[r][4 * g + 2] = d2; sdot[r][4 * g + 3] = d3;
    __syncthreads();
    if (t < 64) {
        float dd = 0.f;
#pragma unroll
        for (int i = 0; i < 16; ++i) dd += sdot[i][t];
        atomicAdd(&g_pos_sim[sslot[t >> 3] * 64 + yin * 8 + (t & 7)], dd * SCALEF);
    }
}

// ---------------------------------------------------------------------------
// 5) persistent GEMM. grid 148, block 512 (16 warps, 4M x 4N, warp 32x32).
//    unit = (q, quarter): 4 chunks (8 mixed). Partial (M,S) -> g_pms.
//    smem: A 64K + B 2x64K = 192K.
// ---------------------------------------------------------------------------
#define SMEM_DYN (3 * TILEB)

__global__ __launch_bounds__(512, 1) void gemm_hmma_kernel() {
    extern __shared__ __align__(128) unsigned char dsm[];
    __shared__ __align__(8) unsigned long long s_mbar[2];
    __shared__ float sh_m[3][128], sh_s[3][128];
    __shared__ int s_unit;

    const int t = threadIdx.x, w = t >> 5, lane = t & 31;
    const unsigned sA_u = sm2u(dsm);
    const unsigned sB_u[2] = { sA_u + TILEB, sA_u + 2 * TILEB };
    const unsigned mb[2] = { sm2u(&s_mbar[0]), sm2u(&s_mbar[1]) };

    if (t == 0) {
        asm volatile("mbarrier.init.shared.b64 [%0], 1;" :: "r"(mb[0]) : "memory");
        asm volatile("mbarrier.init.shared.b64 [%0], 1;" :: "r"(mb[1]) : "memory");
    }
    __syncthreads();

    const int mw = w & 3, nw = w >> 2;            // 4 M-quarters x 4 N-quarters
    const unsigned a_lane = (unsigned)(((lane >> 3) & 1) * 4096 +
                                       ((lane & 7) + 8 * (lane >> 4)) * 16);
    const unsigned a_base0 = sA_u + (unsigned)(mw * 16384) + a_lane;
    const int row_b = (lane & 7) + 8 * ((lane >> 4) & 1);
    const int kc = (lane >> 3) & 1;
    const int rl = row_b & 7;

    const char* negc = (const char*)g_negB;
    const char* posc = (const char*)g_posB;

    unsigned ph[2] = {0u, 0u};

    for (;;) {
        if (t == 0) s_unit = atomicAdd(&g_ctr, 1);
        __syncthreads();
        const int u = s_unit;
        if (u >= NUNITS) break;
        const int q = u >> 2, quarter = u & 3;

        const int info = g_pairinfo[q];
        const int f0 = info & 1, f1 = (info >> 1) & 1;
        const int mixed = (f0 != f1);
        const int nch = mixed ? 8 : 4;

        auto bsrc = [&](int cc) -> const char* {
            const int f = mixed ? ((cc >> 2) ? f1 : f0) : f0;
            const int tile = quarter * 4 + (cc & 3);
            return (f ? posc : negc) + (size_t)tile * TILEB;
        };

        if (t == 0) {
            mbar_expect(mb[0], 2 * TILEB);
            bulk_copy(sA_u, (const char*)g_A + (size_t)q * TILEB, TILEB, mb[0]);
            bulk_copy(sB_u[0], bsrc(0), TILEB, mb[0]);
            mbar_expect(mb[1], TILEB);
            bulk_copy(sB_u[1], bsrc(1), TILEB, mb[1]);
        }

        float m_st[4], s_st[4];
#pragma unroll
        for (int i = 0; i < 4; ++i) { m_st[i] = NEG_HUGE; s_st[i] = 0.f; }

        for (int cc = 0; cc < nch; ++cc) {
            const int buf = cc & 1;
            mbar_wait(mb[buf], ph[buf]);
            ph[buf] ^= 1u;

            const bool active = !mixed || ((mw >> 1) == (cc >> 2));
            if (active) {
                // acc[f(2)][nt(2)][p(2)][h(2)]
                unsigned acc[2][2][2][2];
#pragma unroll
                for (int f = 0; f < 2; ++f)
#pragma unroll
                    for (int nt = 0; nt < 2; ++nt)
#pragma unroll
                        for (int p = 0; p < 2; ++p) {
                            acc[f][nt][p][0] = 0u; acc[f][nt][p][1] = 0u;
                        }
                const unsigned brow0 = sB_u[buf] + (unsigned)((nw * 32 + row_b) * 512);
                const unsigned brow1 = brow0 + 16u * 512u;
#pragma unroll
                for (int ks = 0; ks < 16; ++ks) {
                    unsigned a[2][4];
#pragma unroll
                    for (int f = 0; f < 2; ++f)
                        ldsm4t(a[f][0], a[f][1], a[f][2], a[f][3],
                               a_base0 + (unsigned)(f * 8192 + ks * 256));
                    const int c = 2 * ks + kc;
                    const unsigned coff = (unsigned)(((c & 24) | ((c & 7) ^ rl)) * 16);
#pragma unroll
                    for (int nt = 0; nt < 2; ++nt) {
                        unsigned b0, b1, b2, b3;
                        ldsm4(b0, b1, b2, b3, (nt ? brow1 : brow0) + coff);
#pragma unroll
                        for (int f = 0; f < 2; ++f) {
                            mma_f16(acc[f][nt][0][0], acc[f][nt][0][1],
                                    a[f][0], a[f][1], a[f][2], a[f][3], b0, b1);
                            mma_f16(acc[f][nt][1][0], acc[f][nt][1][1],
                                    a[f][0], a[f][1], a[f][2], a[f][3], b2, b3);
                        }
                    }
                }
#pragma unroll
                for (int idx = 0; idx < 4; ++idx) {
                    const int f = idx >> 1, h = idx & 1;
                    __half2 mx2 = u2h2(acc[f][0][0][h]);
                    mx2 = __hmax2(mx2, u2h2(acc[f][0][1][h]));
                    mx2 = __hmax2(mx2, u2h2(acc[f][1][0][h]));
                    mx2 = __hmax2(mx2, u2h2(acc[f][1][1][h]));
                    float mx = fmaxf(__low2float(mx2), __high2float(mx2));
                    mx = fmaxf(mx, __shfl_xor_sync(~0u, mx, 1));
                    mx = fmaxf(mx, __shfl_xor_sync(~0u, mx, 2));
                    const float nm = fmaxf(m_st[idx], mx);
                    const __half2 nm2 = __float2half2_rn(nm);
                    __half2 s2a = h2ex2(__hsub2(u2h2(acc[f][0][0][h]), nm2));
                    __half2 s2b = h2ex2(__hsub2(u2h2(acc[f][0][1][h]), nm2));
                    s2a = __hadd2(s2a, h2ex2(__hsub2(u2h2(acc[f][1][0][h]), nm2)));
                    s2b = __hadd2(s2b, h2ex2(__hsub2(u2h2(acc[f][1][1][h]), nm2)));
                    const __half2 s2 = __hadd2(s2a, s2b);
                    float su = __low2float(s2) + __high2float(s2);
                    su += __shfl_xor_sync(~0u, su, 1);
                    su += __shfl_xor_sync(~0u, su, 2);
                    s_st[idx] = s_st[idx] * ex2f(m_st[idx] - nm) + su;
                    m_st[idx] = nm;
                }
            }
            __syncthreads();
            if (cc + 2 < nch && t == 0) {
                mbar_expect(mb[buf], TILEB);
                bulk_copy(sB_u[buf], bsrc(cc + 2), TILEB, mb[buf]);
            }
        }

        // combine 4 N-quarter warps per row -> write partial (M,S)
        if (nw > 0 && (lane & 3) == 0) {
#pragma unroll
            for (int idx = 0; idx < 4; ++idx) {
                const int row = mw * 32 + (idx >> 1) * 16 + (lane >> 2) + 8 * (idx & 1);
                sh_m[nw - 1][row] = m_st[idx];
                sh_s[nw - 1][row] = s_st[idx];
            }
        }
        __syncthreads();
        if (nw == 0 && (lane & 3) == 0) {
#pragma unroll
            for (int idx = 0; idx < 4; ++idx) {
                const int row = mw * 32 + (idx >> 1) * 16 + (lane >> 2) + 8 * (idx & 1);
                float M = m_st[idx], S = s_st[idx];
#pragma unroll
                for (int v = 0; v < 3; ++v) {
                    const float m2 = sh_m[v][row], s2 = sh_s[v][row];
                    const float NM = fmaxf(M, m2);
                    S = S * ex2f(M - NM) + s2 * ex2f(m2 - NM);
                    M = NM;
                }
                g_pms[u * 128 + row] = make_float2(M, S);
            }
        }
        __syncthreads();
    }
}

// ---------------------------------------------------------------------------
// 6) merge 4 quarter-partials per row -> loss; block partial sums
// ---------------------------------------------------------------------------
__global__ void merge_kernel() {
    __shared__ float sred[8];
    const int t = threadIdx.x, blk = blockIdx.x;
    const int r = blk * 256 + t;
    const int q = r >> 7, row = r & 127;
    float M = NEG_HUGE, S = 0.f;
#pragma unroll
    for (int quarter = 0; quarter < 4; ++quarter) {
        const float2 ms = g_pms[((q * 4 + quarter) * 128) + row];
        const float NM = fmaxf(M, ms.x);
        S = S * ex2f(M - NM) + ms.y * ex2f(ms.x - NM);
        M = NM;
    }
    const float p = g_pos_sim[r];
    const float mf = fmaxf(M, p);
    const float ep = ex2f(p - mf);
    const float denom = S * ex2f(M - mf) + ep + EPSV;
    float loss = -logf(ep / denom + EPSV);
#pragma unroll
    for (int o = 16; o; o >>= 1) loss += __shfl_xor_sync(~0u, loss, o);
    if ((t & 31) == 0) sred[t >> 5] = loss;
    __syncthreads();
    if (t == 0) {
        float tot = 0.f;
#pragma unroll
        for (int i = 0; i < 8; ++i) tot += sred[i];
        g_part[blk] = tot;
    }
}

// ---------------------------------------------------------------------------
// 7) final reduction (128 partials)
// ---------------------------------------------------------------------------
__global__ void finalize_kernel(float* __restrict__ out) {
    __shared__ float sred[4];
    const int t = threadIdx.x;
    float v = g_part[t];
#pragma unroll
    for (int o = 16; o; o >>= 1) v += __shfl_xor_sync(~0u, v, o);
    if ((t & 31) == 0) sred[t >> 5] = v;
    __syncthreads();
    if (t == 0) {
        float tot = sred[0] + sred[1] + sred[2] + sred[3];
        out[0] = tot * (1.f / 32768.f);
    }
}

// ---------------------------------------------------------------------------
extern "C" void kernel_launch(void* const* d_in, const int* in_sizes, int n_in,
                              void* d_out, int out_size) {
    const float* mainp = (const float*)d_in[0];
    const float* emap  = (const float*)d_in[1];
    const float* lab   = (const float*)d_in[2];
    const float* neg   = (const float*)d_in[3];
    const float* pos   = (const float*)d_in[4];
    float* out = (float*)d_out;

    cudaFuncSetAttribute(gemm_hmma_kernel,
                         cudaFuncAttributeMaxDynamicSharedMemorySize, SMEM_DYN);

    label_kernel<<<NPATCH, 256>>>(lab);
    perm_kernel<<<1, 512>>>();
    convert_bank_kernel<<<64, 256>>>(neg, pos);
    convert_anchor_kernel<<<1024, 256>>>(mainp, emap);
    gemm_hmma_kernel<<<148, 512, SMEM_DYN>>>();
    merge_kernel<<<128, 256>>>();
    finalize_kernel<<<1, 128>>>(out);
}

// round 17
// speedup vs baseline: 1.4014x; 1.1155x over previous
#include <cuda_runtime.h>
#include <cuda_fp16.h>
#include <cstdint>

// ---------------------------------------------------------------------------
// ContrastivePatchLoss — R11 champion + fused conversion launch + fused
// merge/finalize (last-block pattern).
// ---------------------------------------------------------------------------

#define NPATCH   512
#define ROWS_TOT 32768
#define NBANK    2048
#define EPSV     1e-5f
#define SCALEF   2.8853900817779268f   // (1/0.5) * log2(e)
#define NEG_HUGE (-1e30f)
#define TILEB    65536                 // 128 rows x 512 B
#define NUNITS   1024                  // 256 q x 4 col-quarters

// g_A blocked: [slot(512)][yin(8)][c(256)][xin(8)] fp16
__device__ __half g_A[ROWS_TOT * 256];
// banks pre-swizzled: [tile(16)][row(128)][c'(32) x 16B], c' = (c&24)|((c^row)&7)
__device__ __half g_negB[NBANK * 256];
__device__ __half g_posB[NBANK * 256];
__device__ float g_pos_sim[ROWS_TOT];
__device__ int   g_flags[NPATCH];
__device__ int   g_slot[NPATCH];
__device__ int   g_pairinfo[256];
__device__ int   g_ctr;
__device__ int   g_mdone;
__device__ float2 g_pms[NUNITS * 128];            // per-(unit,row) partial (M,S)
__device__ float g_part[128];

// ---------------------------------------------------------------------------
__device__ __forceinline__ unsigned sm2u(const void* p) {
    return (unsigned)__cvta_generic_to_shared(p);
}
__device__ __forceinline__ float ex2f(float x) {
    float y; asm("ex2.approx.f32 %0, %1;" : "=f"(y) : "f"(x)); return y;
}
__device__ __forceinline__ __half2 h2ex2(__half2 x) {
    __half2 y;
    asm("ex2.approx.f16x2 %0, %1;" : "=r"(*(unsigned*)&y) : "r"(*(unsigned*)&x));
    return y;
}
__device__ __forceinline__ __half2 u2h2(unsigned u) { return *(__half2*)&u; }
__device__ __forceinline__ void ldsm4(unsigned& r0, unsigned& r1, unsigned& r2, unsigned& r3,
                                      unsigned addr) {
    asm volatile("ldmatrix.sync.aligned.m8n8.x4.shared.b16 {%0,%1,%2,%3}, [%4];\n"
                 : "=r"(r0), "=r"(r1), "=r"(r2), "=r"(r3) : "r"(addr));
}
__device__ __forceinline__ void ldsm4t(unsigned& r0, unsigned& r1, unsigned& r2, unsigned& r3,
                                       unsigned addr) {
    asm volatile("ldmatrix.sync.aligned.m8n8.x4.trans.shared.b16 {%0,%1,%2,%3}, [%4];\n"
                 : "=r"(r0), "=r"(r1), "=r"(r2), "=r"(r3) : "r"(addr));
}
__device__ __forceinline__ void mma_f16(unsigned& c0, unsigned& c1,
                                        unsigned a0, unsigned a1, unsigned a2, unsigned a3,
                                        unsigned b0, unsigned b1) {
    asm volatile("mma.sync.aligned.m16n8k16.row.col.f16.f16.f16.f16 "
                 "{%0,%1},{%2,%3,%4,%5},{%6,%7},{%0,%1};\n"
                 : "+r"(c0), "+r"(c1)
                 : "r"(a0), "r"(a1), "r"(a2), "r"(a3), "r"(b0), "r"(b1));
}
__device__ __forceinline__ void mbar_wait(unsigned addr, unsigned parity) {
    asm volatile("{\n\t.reg .pred P;\n"
                 "W%=:\n\tmbarrier.try_wait.parity.shared.b64 P, [%0], %1;\n"
                 "\t@P bra D%=;\n\tbra W%=;\nD%=:\n\t}"
                 :: "r"(addr), "r"(parity) : "memory");
}
__device__ __forceinline__ void mbar_expect(unsigned addr, unsigned bytes) {
    asm volatile("mbarrier.arrive.expect_tx.shared.b64 _, [%0], %1;"
                 :: "r"(addr), "r"(bytes) : "memory");
}
__device__ __forceinline__ void bulk_copy(unsigned dst, const void* src, unsigned bytes,
                                          unsigned mbar) {
    asm volatile("cp.async.bulk.shared::cluster.global.mbarrier::complete_tx::bytes "
                 "[%0], [%1], %2, [%3];"
                 :: "r"(dst), "l"(src), "r"(bytes), "r"(mbar) : "memory");
}

// ---------------------------------------------------------------------------
// 1) label patch means -> flags; zeroes g_pos_sim
// ---------------------------------------------------------------------------
__global__ void label_kernel(const float* __restrict__ lab) {
    __shared__ float sred[8];
    const int p = blockIdx.x, t = threadIdx.x;
    if (t < 64) g_pos_sim[p * 64 + t] = 0.f;
    const int b = p >> 6, j = (p >> 3) & 7, k = p & 7;
    const float* base = lab + (size_t)b * 65536 + (size_t)j * 32 * 256 + k * 32;
    float sum = 0.f;
#pragma unroll
    for (int it = 0; it < 4; ++it) {
        int u = t + 256 * it;
        int y = u >> 5, x = u & 31;
        sum += base[y * 256 + x];
    }
#pragma unroll
    for (int o = 16; o; o >>= 1) sum += __shfl_xor_sync(~0u, sum, o);
    if ((t & 31) == 0) sred[t >> 5] = sum;
    __syncthreads();
    if (t == 0) {
        float s2 = 0.f;
#pragma unroll
        for (int i = 0; i < 8; ++i) s2 += sred[i];
        g_flags[p] = (s2 * (1.f / 1024.f) < 0.1f) ? 1 : 0;
    }
}

// ---------------------------------------------------------------------------
// 2) permutation + counter resets
// ---------------------------------------------------------------------------
__global__ void perm_kernel() {
    __shared__ int sc[512], sflag[512];
    const int t = threadIdx.x;
    if (t == 0) { g_ctr = 0; g_mdone = 0; }
    const int f = g_flags[t];
    sc[t] = f;
    __syncthreads();
    for (int off = 1; off < 512; off <<= 1) {
        int add = (t >= off) ? sc[t - off] : 0;
        __syncthreads();
        sc[t] += add;
        __syncthreads();
    }
    const int npos = sc[511];
    const int slot = f ? (sc[t] - 1) : (npos + t - sc[t]);
    g_slot[t] = slot;
    sflag[slot] = f;
    __syncthreads();
    if (t < 256) g_pairinfo[t] = sflag[2 * t] | (sflag[2 * t + 1] << 1);
}

// ---------------------------------------------------------------------------
// 3) fused conversion: blocks 0-63 = bank units; blocks 64+ = anchor units.
// ---------------------------------------------------------------------------
__global__ void conv_kernel(const float* __restrict__ mainp,
                            const float* __restrict__ emap,
                            const float* __restrict__ neg,
                            const float* __restrict__ pos) {
    __shared__ __align__(16) unsigned char smem[34048];  // bank sT / anchor sdot+sslot
    const int t = threadIdx.x;
    if (blockIdx.x < 64) {
        // ---- bank unit ----
        __half (*sT)[66] = (__half(*)[66])smem;
        const int blk = blockIdx.x;
        const int bank = blk >> 5, l = blk & 31;
        const float* src = (bank ? pos : neg) + (size_t)l * 16384;
#pragma unroll 4
        for (int it = 0; it < 64; ++it) {
            int u = t + 256 * it;
            int c = u >> 6, s = u & 63;
            sT[c][s] = __float2half(src[c * 64 + s]);
        }
        __syncthreads();
        unsigned* dst32 = (unsigned*)((bank ? g_posB : g_negB));
        const int tile = l >> 1;
        const int rbase = (l & 1) * 64;
#pragma unroll 4
        for (int it = 0; it < 32; ++it) {
            int u = t + 256 * it;
            int s = u >> 7, cc = u & 127;
            unsigned lo = __half_as_ushort(sT[2 * cc][s]);
            unsigned hi = __half_as_ushort(sT[2 * cc + 1][s]);
            const int row = rbase + s;
            const int c16 = cc >> 2;
            const int csw = (c16 & 24) | ((c16 ^ row) & 7);
            dst32[(tile * 65536 + row * 512 + csw * 16 + (cc & 3) * 4) >> 2] = (hi << 16) | lo;
        }
        return;
    }
    // ---- anchor unit (R11 layout) ----
    float (*sdot)[65] = (float(*)[65])smem;
    int* sslot = (int*)(smem + 16 * 65 * 4);
    const int bid0 = blockIdx.x - 64;
    const int chalf = bid0 >> 9;
    const int bid = bid0 & 511;
    const int b = bid >> 6, y = bid & 63;
    const int j = y >> 3, yin = y & 7;
    if (t < 8) sslot[t] = g_slot[b * 64 + j * 8 + t];
    __syncthreads();

    const int g = t & 15, r = t >> 4;
    const int kslot = g >> 1;
    const unsigned xh = (unsigned)(g & 1);
    const size_t base4 = ((size_t)b * 256 * 64 + y) * 16 + g;
    const float4* mp = (const float4*)mainp;
    const float4* ep = (const float4*)emap;
    uint2* Aout = (uint2*)g_A;

    float d0 = 0.f, d1 = 0.f, d2 = 0.f, d3 = 0.f;
#pragma unroll
    for (int it = 0; it < 8; ++it) {
        const int c = r + 16 * it + chalf * 128;
        const size_t o = base4 + (size_t)c * 1024;
        const float4 mv = mp[o];
        const float4 ev = ep[o];
        d0 += mv.x * ev.x; d1 += mv.y * ev.y; d2 += mv.z * ev.z; d3 += mv.w * ev.w;
        const __half2 lo = __floats2half2_rn(mv.x * SCALEF, mv.y * SCALEF);
        const __half2 hi = __floats2half2_rn(mv.z * SCALEF, mv.w * SCALEF);
        uint2 v;
        v.x = *(const unsigned*)&lo;
        v.y = *(const unsigned*)&hi;
        Aout[(size_t)((sslot[kslot] * 8 + yin) * 256 + c) * 2 + xh] = v;
    }
    sdot[r][4 * g + 0] = d0; sdot[r][4 * g + 1] = d1;
    sdot[r][4 * g + 2] = d2; sdot[r][4 * g + 3] = d3;
    __syncthreads();
    if (t < 64) {
        float dd = 0.f;
#pragma unroll
        for (int i = 0; i < 16; ++i) dd += sdot[i][t];
        atomicAdd(&g_pos_sim[sslot[t >> 3] * 64 + yin * 8 + (t & 7)], dd * SCALEF);
    }
}

// ---------------------------------------------------------------------------
// 4) persistent GEMM. grid 148, block 256 (8 warps, 2M x 4N, warp 64x32).
// ---------------------------------------------------------------------------
#define SMEM_DYN (3 * TILEB)

__global__ __launch_bounds__(256, 1) void gemm_hmma_kernel() {
    extern __shared__ __align__(128) unsigned char dsm[];
    __shared__ __align__(8) unsigned long long s_mbar[2];
    __shared__ float sh_m[3][128], sh_s[3][128];
    __shared__ int s_unit;

    const int t = threadIdx.x, w = t >> 5, lane = t & 31;
    const unsigned sA_u = sm2u(dsm);
    const unsigned sB_u[2] = { sA_u + TILEB, sA_u + 2 * TILEB };
    const unsigned mb[2] = { sm2u(&s_mbar[0]), sm2u(&s_mbar[1]) };

    if (t == 0) {
        asm volatile("mbarrier.init.shared.b64 [%0], 1;" :: "r"(mb[0]) : "memory");
        asm volatile("mbarrier.init.shared.b64 [%0], 1;" :: "r"(mb[1]) : "memory");
    }
    __syncthreads();

    const int mw = w & 1, nw = w >> 1;            // 2 M-halves x 4 N-quarters
    const unsigned a_lane = (unsigned)(((lane >> 3) & 1) * 4096 +
                                       ((lane & 7) + 8 * (lane >> 4)) * 16);
    const unsigned a_base0 = sA_u + (unsigned)(mw * 32768) + a_lane;
    const int row_b = (lane & 7) + 8 * ((lane >> 4) & 1);
    const int kc = (lane >> 3) & 1;
    const int rl = row_b & 7;

    const char* negc = (const char*)g_negB;
    const char* posc = (const char*)g_posB;

    unsigned ph[2] = {0u, 0u};

    for (;;) {
        if (t == 0) s_unit = atomicAdd(&g_ctr, 1);
        __syncthreads();
        const int u = s_unit;
        if (u >= NUNITS) break;
        const int q = u >> 2, quarter = u & 3;

        const int info = g_pairinfo[q];
        const int f0 = info & 1, f1 = (info >> 1) & 1;
        const int mixed = (f0 != f1);
        const int nch = mixed ? 8 : 4;
        const int shift = mixed ? 2 : 8;

        auto bsrc = [&](int cc) -> const char* {
            const int f = mixed ? ((cc >> 2) ? f1 : f0) : f0;
            const int tile = quarter * 4 + (cc & 3);
            return (f ? posc : negc) + (size_t)tile * TILEB;
        };

        if (t == 0) {
            mbar_expect(mb[0], 2 * TILEB);
            bulk_copy(sA_u, (const char*)g_A + (size_t)q * TILEB, TILEB, mb[0]);
            bulk_copy(sB_u[0], bsrc(0), TILEB, mb[0]);
            mbar_expect(mb[1], TILEB);
            bulk_copy(sB_u[1], bsrc(1), TILEB, mb[1]);
        }

        float m_st[8], s_st[8];
#pragma unroll
        for (int i = 0; i < 8; ++i) { m_st[i] = NEG_HUGE; s_st[i] = 0.f; }

        for (int cc = 0; cc < nch; ++cc) {
            const int buf = cc & 1;
            mbar_wait(mb[buf], ph[buf]);
            ph[buf] ^= 1u;

            const bool active = !mixed || (mw == (cc >> shift));
            if (active) {
                unsigned acc[4][2][2][2];
#pragma unroll
                for (int f = 0; f < 4; ++f)
#pragma unroll
                    for (int nt = 0; nt < 2; ++nt)
#pragma unroll
                        for (int p = 0; p < 2; ++p) {
                            acc[f][nt][p][0] = 0u; acc[f][nt][p][1] = 0u;
                        }
                const unsigned brow0 = sB_u[buf] + (unsigned)((nw * 32 + row_b) * 512);
                const unsigned brow1 = brow0 + 16u * 512u;
#pragma unroll
                for (int ks = 0; ks < 16; ++ks) {
                    unsigned a[4][4];
#pragma unroll
                    for (int f = 0; f < 4; ++f)
                        ldsm4t(a[f][0], a[f][1], a[f][2], a[f][3],
                               a_base0 + (unsigned)(f * 8192 + ks * 256));
                    const int c = 2 * ks + kc;
                    const unsigned coff = (unsigned)(((c & 24) | ((c & 7) ^ rl)) * 16);
#pragma unroll
                    for (int nt = 0; nt < 2; ++nt) {
                        unsigned b0, b1, b2, b3;
                        ldsm4(b0, b1, b2, b3, (nt ? brow1 : brow0) + coff);
#pragma unroll
                        for (int f = 0; f < 4; ++f) {
                            mma_f16(acc[f][nt][0][0], acc[f][nt][0][1],
                                    a[f][0], a[f][1], a[f][2], a[f][3], b0, b1);
                            mma_f16(acc[f][nt][1][0], acc[f][nt][1][1],
                                    a[f][0], a[f][1], a[f][2], a[f][3], b2, b3);
                        }
                    }
                }
#pragma unroll
                for (int idx = 0; idx < 8; ++idx) {
                    const int f = idx >> 1, h = idx & 1;
                    __half2 mx2 = u2h2(acc[f][0][0][h]);
                    mx2 = __hmax2(mx2, u2h2(acc[f][0][1][h]));
                    mx2 = __hmax2(mx2, u2h2(acc[f][1][0][h]));
                    mx2 = __hmax2(mx2, u2h2(acc[f][1][1][h]));
                    float mx = fmaxf(__low2float(mx2), __high2float(mx2));
                    mx = fmaxf(mx, __shfl_xor_sync(~0u, mx, 1));
                    mx = fmaxf(mx, __shfl_xor_sync(~0u, mx, 2));
                    const float nm = fmaxf(m_st[idx], mx);
                    const __half2 nm2 = __float2half2_rn(nm);
                    __half2 s2a = h2ex2(__hsub2(u2h2(acc[f][0][0][h]), nm2));
                    __half2 s2b = h2ex2(__hsub2(u2h2(acc[f][0][1][h]), nm2));
                    s2a = __hadd2(s2a, h2ex2(__hsub2(u2h2(acc[f][1][0][h]), nm2)));
                    s2b = __hadd2(s2b, h2ex2(__hsub2(u2h2(acc[f][1][1][h]), nm2)));
                    const __half2 s2 = __hadd2(s2a, s2b);
                    float su = __low2float(s2) + __high2float(s2);
                    su += __shfl_xor_sync(~0u, su, 1);
                    su += __shfl_xor_sync(~0u, su, 2);
                    s_st[idx] = s_st[idx] * ex2f(m_st[idx] - nm) + su;
                    m_st[idx] = nm;
                }
            }
            __syncthreads();
            if (cc + 2 < nch && t == 0) {
                mbar_expect(mb[buf], TILEB);
                bulk_copy(sB_u[buf], bsrc(cc + 2), TILEB, mb[buf]);
            }
        }

        if (nw > 0 && (lane & 3) == 0) {
#pragma unroll
            for (int idx = 0; idx < 8; ++idx) {
                const int row = mw * 64 + (idx >> 1) * 16 + (lane >> 2) + 8 * (idx & 1);
                sh_m[nw - 1][row] = m_st[idx];
                sh_s[nw - 1][row] = s_st[idx];
            }
        }
        __syncthreads();
        if (nw == 0 && (lane & 3) == 0) {
#pragma unroll
            for (int idx = 0; idx < 8; ++idx) {
                const int row = mw * 64 + (idx >> 1) * 16 + (lane >> 2) + 8 * (idx & 1);
                float M = m_st[idx], S = s_st[idx];
#pragma unroll
                for (int v = 0; v < 3; ++v) {
                    const float m2 = sh_m[v][row], s2 = sh_s[v][row];
                    const float NM = fmaxf(M, m2);
                    S = S * ex2f(M - NM) + s2 * ex2f(m2 - NM);
                    M = NM;
                }
                g_pms[u * 128 + row] = make_float2(M, S);
            }
        }
        __syncthreads();
    }
}

// ---------------------------------------------------------------------------
// 5) merge + fused finalize (last block reduces 128 partials in fixed order)
// ---------------------------------------------------------------------------
__global__ void merge_kernel(float* __restrict__ out) {
    __shared__ float sred[8];
    __shared__ int s_last;
    const int t = threadIdx.x, blk = blockIdx.x;
    const int r = blk * 256 + t;
    const int q = r >> 7, row = r & 127;
    float M = NEG_HUGE, S = 0.f;
#pragma unroll
    for (int quarter = 0; quarter < 4; ++quarter) {
        const float2 ms = g_pms[((q * 4 + quarter) * 128) + row];
        const float NM = fmaxf(M, ms.x);
        S = S * ex2f(M - NM) + ms.y * ex2f(ms.x - NM);
        M = NM;
    }
    const float p = g_pos_sim[r];
    const float mf = fmaxf(M, p);
    const float ep = ex2f(p - mf);
    const float denom = S * ex2f(M - mf) + ep + EPSV;
    float loss = -logf(ep / denom + EPSV);
#pragma unroll
    for (int o = 16; o; o >>= 1) loss += __shfl_xor_sync(~0u, loss, o);
    if ((t & 31) == 0) sred[t >> 5] = loss;
    __syncthreads();
    if (t == 0) {
        float tot = 0.f;
#pragma unroll
        for (int i = 0; i < 8; ++i) tot += sred[i];
        g_part[blk] = tot;
        __threadfence();
        s_last = (atomicAdd(&g_mdone, 1) == 127);
    }
    __syncthreads();
    if (s_last) {
        // last block: deterministic fixed-order reduction of 128 partials
        float v = (t < 128) ? *(volatile float*)&g_part[t] : 0.f;
#pragma unroll
        for (int o = 16; o; o >>= 1) v += __shfl_xor_sync(~0u, v, o);
        if ((t & 31) == 0) sred[t >> 5] = v;
        __syncthreads();
        if (t == 0)
            out[0] = (sred[0] + sred[1] + sred[2] + sred[3]) * (1.f / 32768.f);
    }
}

// ---------------------------------------------------------------------------
extern "C" void kernel_launch(void* const* d_in, const int* in_sizes, int n_in,
                              void* d_out, int out_size) {
    const float* mainp = (const float*)d_in[0];
    const float* emap  = (const float*)d_in[1];
    const float* lab   = (const float*)d_in[2];
    const float* neg   = (const float*)d_in[3];
    const float* pos   = (const float*)d_in[4];
    float* out = (float*)d_out;

    cudaFuncSetAttribute(gemm_hmma_kernel,
                         cudaFuncAttributeMaxDynamicSharedMemorySize, SMEM_DYN);

    label_kernel<<<NPATCH, 256>>>(lab);
    perm_kernel<<<1, 512>>>();
    conv_kernel<<<1088, 256>>>(mainp, emap, neg, pos);
    gemm_hmma_kernel<<<148, 256, SMEM_DYN>>>();
    merge_kernel<<<128, 256>>>(out);
}